// round 16
// baseline (speedup 1.0000x reference)
#include <cuda_runtime.h>

// FullyConnectedTensorProduct: B=2^20, MUL=8, DIM=32, 4 paths of 8x8x8.
// R16: R15 + register-resident weights. Each lane holds its 32 uint2
// B-fragment pairs (one per kk-block) in registers, loaded once via 16
// LDS.128 (weights restaged [wIdx][kk]-major) -> mainloop has ZERO weight
// loads (-64 LDS / -128 L1 wavefronts per warp). Input caches are phased
// (s1 in kk0..7, v1 loaded for kk8..15) so peak regs ~160 fit 3 blocks/SM.
// Raw-bit tf32 A; EPITCH=68 staging; store mapping as validated in R13-R15.

typedef unsigned int u32;

#define ALPHA_F     0.08838834764831845f   /* 1/sqrt(128) */
#define INV_SQRT3_F 0.5773502691896258f
#define EPITCH 68

static __device__ __forceinline__ u32 cvt_tf32(float f) {
    u32 r;
    asm("cvt.rna.tf32.f32 %0, %1;" : "=r"(r) : "f"(f));
    return r;
}
static __device__ __forceinline__ u32 tf32_raw(float f) {
    return __float_as_uint(f);
}

static __device__ __forceinline__ void mma_tf32(float c[4],
        u32 a0, u32 a1, u32 a2, u32 a3, uint2 wv)
{
    asm("mma.sync.aligned.m16n8k8.row.col.f32.tf32.tf32.f32 "
        "{%0,%1,%2,%3}, {%4,%5,%6,%7}, {%8,%9}, {%0,%1,%2,%3};"
        : "+f"(c[0]), "+f"(c[1]), "+f"(c[2]), "+f"(c[3])
        : "r"(a0), "r"(a1), "r"(a2), "r"(a3), "r"(wv.x), "r"(wv.y));
}

__global__ __launch_bounds__(128, 3)
void fctp_kernel(const float* __restrict__ x1,
                 const float* __restrict__ x2,
                 const float* __restrict__ wt,
                 float* __restrict__ out)
{
    extern __shared__ __align__(16) float smem[];
    float* st = smem + 2048;          // 128 * EPITCH staging

    const int tid = threadIdx.x;
    const size_t eBase = (size_t)blockIdx.x * 128;

    // ---- stage weights [wIdx][kk]-major: u32 pos i = wIdx*64 + kk*2 + j.
    //      src col c = kk*8 + t + 4*j (kk 0..31), src idx = c*8 + g.
    //      INV_SQRT3 folded into W1 range [512,1024).
#pragma unroll
    for (int c = 0; c < 16; c++) {
        int i    = tid + c * 128;
        int wIdx = i >> 6;
        int kk   = (i >> 1) & 31;
        int j    = i & 1;
        int t_ = wIdx >> 3, g_ = wIdx & 7;
        int src = (kk * 8 + t_ + 4 * j) * 8 + g_;
        float s = ((src >> 9) == 1) ? INV_SQRT3_F : 1.0f;
        ((u32*)smem)[i] = cvt_tf32(__ldg(wt + src) * s);
    }

    // ---- stage inputs (STS.128): x1*ALPHA at [0..31], x2 at [32..63] ----
    {
        const float4* g1 = (const float4*)(x1 + eBase * 32);
        const float4* g2 = (const float4*)(x2 + eBase * 32);
#pragma unroll
        for (int c = 0; c < 8; c++) {
            int lin = tid + c * 128;
            int e = lin >> 3, j = (lin & 7) << 2;
            float4 a = g1[lin];
            a.x *= ALPHA_F; a.y *= ALPHA_F; a.z *= ALPHA_F; a.w *= ALPHA_F;
            *(float4*)(st + e * EPITCH + j) = a;
            float4 b = g2[lin];
            *(float4*)(st + e * EPITCH + 32 + j) = b;
        }
    }
    __syncthreads();

    const int lane = tid & 31;
    const int g = lane >> 2;
    const int t = lane & 3;
    const int wBase = (tid >> 5) * 32;
    const int wIdx = t * 8 + g;

    // ---- one-time: lane's 32 B-fragment pairs into registers ----
    uint2 wreg[32];
    {
        const u32* wb = ((const u32*)smem) + wIdx * 64;
#pragma unroll
        for (int q = 0; q < 16; q++) {
            uint4 w4 = *(const uint4*)(wb + q * 4);
            wreg[2 * q]     = make_uint2(w4.x, w4.y);
            wreg[2 * q + 1] = make_uint2(w4.z, w4.w);
        }
    }

#pragma unroll
    for (int rb = 0; rb < 2; rb++) {
        float* Rlo = st + (wBase + rb * 16 + g) * EPITCH;
        float* Rhi = Rlo + 8 * EPITCH;

        // ---- s2 / v2 scalars (v in {t, t+4}) ----
        float s2l[2], s2h[2], v2l[2][3], v2h[2][3];
#pragma unroll
        for (int j = 0; j < 2; j++) {
            int v = t + 4 * j;
            s2l[j] = Rlo[32 + v];
            s2h[j] = Rhi[32 + v];
#pragma unroll
            for (int k = 0; k < 3; k++) {
                v2l[j][k] = Rlo[40 + v * 3 + k];
                v2h[j][k] = Rhi[40 + v * 3 + k];
            }
        }

        float C0a[4] = {0.f, 0.f, 0.f, 0.f};
        float C0b[4] = {0.f, 0.f, 0.f, 0.f};
        float C1[3][4] = {};

        // ======== phase 1: kk 0..7 (s1-based); s1 cache lives here only ====
        {
            float4 lq0 = *(const float4*)(Rlo + 0);
            float4 lq1 = *(const float4*)(Rlo + 4);
            float4 hq0 = *(const float4*)(Rhi + 0);
            float4 hq1 = *(const float4*)(Rhi + 4);
            float s1l[8] = {lq0.x, lq0.y, lq0.z, lq0.w,
                            lq1.x, lq1.y, lq1.z, lq1.w};
            float s1h[8] = {hq0.x, hq0.y, hq0.z, hq0.w,
                            hq1.x, hq1.y, hq1.z, hq1.w};
#pragma unroll
            for (int kk = 0; kk < 8; kk++) {
                mma_tf32(C0a,
                         tf32_raw(s1l[kk] * s2l[0]), tf32_raw(s1h[kk] * s2h[0]),
                         tf32_raw(s1l[kk] * s2l[1]), tf32_raw(s1h[kk] * s2h[1]),
                         wreg[kk]);
#pragma unroll
                for (int k = 0; k < 3; k++)
                    mma_tf32(C1[k],
                             tf32_raw(s1l[kk] * v2l[0][k]),
                             tf32_raw(s1h[kk] * v2h[0][k]),
                             tf32_raw(s1l[kk] * v2l[1][k]),
                             tf32_raw(s1h[kk] * v2h[1][k]),
                             wreg[16 + kk]);
            }
        }

        // ======== phase 2: kk 8..15 (v1-based); v1 cache loaded now ========
        {
            float v1l[24], v1h[24];
#pragma unroll
            for (int q = 0; q < 6; q++) {
                float4 a = *(const float4*)(Rlo + 8 + 4 * q);
                v1l[4*q+0] = a.x; v1l[4*q+1] = a.y;
                v1l[4*q+2] = a.z; v1l[4*q+3] = a.w;
                float4 b = *(const float4*)(Rhi + 8 + 4 * q);
                v1h[4*q+0] = b.x; v1h[4*q+1] = b.y;
                v1h[4*q+2] = b.z; v1h[4*q+3] = b.w;
            }
#pragma unroll
            for (int kk = 8; kk < 16; kk++) {
                int u = kk - 8;
                u32 a0 = tf32_raw(v1l[u*3+0] * v2l[0][0] + v1l[u*3+1] * v2l[0][1]
                                  + v1l[u*3+2] * v2l[0][2]);
                u32 a1 = tf32_raw(v1h[u*3+0] * v2h[0][0] + v1h[u*3+1] * v2h[0][1]
                                  + v1h[u*3+2] * v2h[0][2]);
                u32 a2 = tf32_raw(v1l[u*3+0] * v2l[1][0] + v1l[u*3+1] * v2l[1][1]
                                  + v1l[u*3+2] * v2l[1][2]);
                u32 a3 = tf32_raw(v1h[u*3+0] * v2h[1][0] + v1h[u*3+1] * v2h[1][1]
                                  + v1h[u*3+2] * v2h[1][2]);
                mma_tf32(C0b, a0, a1, a2, a3, wreg[kk]);
#pragma unroll
                for (int k = 0; k < 3; k++)
                    mma_tf32(C1[k],
                             tf32_raw(v1l[u*3+k] * s2l[0]),
                             tf32_raw(v1h[u*3+k] * s2h[0]),
                             tf32_raw(v1l[u*3+k] * s2l[1]),
                             tf32_raw(v1h[u*3+k] * s2h[1]),
                             wreg[16 + kk]);
            }
        }

        // ---- vector stores into own staging rows ----
        // C layout: c0:(g,2t) c1:(g,2t+1) c2:(g+8,2t) c3:(g+8,2t+1)
        *(float2*)(Rlo + 2 * t) = make_float2(C0a[0] + C0b[0], C0a[1] + C0b[1]);
        *(float2*)(Rhi + 2 * t) = make_float2(C0a[2] + C0b[2], C0a[3] + C0b[3]);
        *(float2*)(Rlo + 8 + 6 * t)     = make_float2(C1[0][0], C1[1][0]);
        *(float2*)(Rlo + 8 + 6 * t + 2) = make_float2(C1[2][0], C1[0][1]);
        *(float2*)(Rlo + 8 + 6 * t + 4) = make_float2(C1[1][1], C1[2][1]);
        *(float2*)(Rhi + 8 + 6 * t)     = make_float2(C1[0][2], C1[1][2]);
        *(float2*)(Rhi + 8 + 6 * t + 2) = make_float2(C1[2][2], C1[0][3]);
        *(float2*)(Rhi + 8 + 6 * t + 4) = make_float2(C1[1][3], C1[2][3]);
    }

    __syncthreads();

    // ---- coalesced drain (LDS.128 -> STG.128) ----
    {
        float4* go = (float4*)(out + eBase * 32);
#pragma unroll
        for (int c = 0; c < 8; c++) {
            int lin = tid + c * 128;
            int e = lin >> 3, j = (lin & 7) << 2;
            go[lin] = *(const float4*)(st + e * EPITCH + j);
        }
    }
}

extern "C" void kernel_launch(void* const* d_in, const int* in_sizes, int n_in,
                              void* d_out, int out_size)
{
    const float* x1 = (const float*)d_in[0];
    const float* x2 = (const float*)d_in[1];
    const float* wt = (const float*)d_in[2];
    float* out = (float*)d_out;

    int nelem  = out_size / 32;                            // 2^20
    int blocks = nelem / 128;                              // 128 elements/block
    size_t smem = (2048 + 128 * EPITCH) * sizeof(float);   // 43008 B

    static bool attr_set = false;
    if (!attr_set) {
        cudaFuncSetAttribute(fctp_kernel,
                             cudaFuncAttributeMaxDynamicSharedMemorySize,
                             (int)smem);
        attr_set = true;
    }
    fctp_kernel<<<blocks, 128, smem>>>(x1, x2, wt, out);
}

// round 17
// speedup vs baseline: 2.0868x; 2.0868x over previous
#include <cuda_runtime.h>

// FullyConnectedTensorProduct: B=2^20, MUL=8, DIM=32, 4 paths of 8x8x8.
// R17: R15 champion structure, with the s1 phase (kk 0..7) restructured so
// each weight pair (wv1, wv2) is loaded ONCE and feeds BOTH rb halves
// (weight LDS 64 -> 48 per warp, -32 L1 wavefronts). v1 phase stays per-rb
// (v1 caches for both halves don't fit 128 regs). C0a/C0b merged. Scalar
// A-forming, raw-bit tf32, EPITCH=68 staging, paired weights [kk][wIdx].

typedef unsigned int u32;

#define ALPHA_F     0.08838834764831845f   /* 1/sqrt(128) */
#define INV_SQRT3_F 0.5773502691896258f
#define EPITCH 68

static __device__ __forceinline__ u32 cvt_tf32(float f) {
    u32 r;
    asm("cvt.rna.tf32.f32 %0, %1;" : "=r"(r) : "f"(f));
    return r;
}
static __device__ __forceinline__ u32 tf32_raw(float f) {
    return __float_as_uint(f);
}

static __device__ __forceinline__ void mma_tf32(float c[4],
        u32 a0, u32 a1, u32 a2, u32 a3, uint2 wv)
{
    asm("mma.sync.aligned.m16n8k8.row.col.f32.tf32.tf32.f32 "
        "{%0,%1,%2,%3}, {%4,%5,%6,%7}, {%8,%9}, {%0,%1,%2,%3};"
        : "+f"(c[0]), "+f"(c[1]), "+f"(c[2]), "+f"(c[3])
        : "r"(a0), "r"(a1), "r"(a2), "r"(a3), "r"(wv.x), "r"(wv.y));
}

__global__ __launch_bounds__(128, 4)
void fctp_kernel(const float* __restrict__ x1,
                 const float* __restrict__ x2,
                 const float* __restrict__ wt,
                 float* __restrict__ out)
{
    extern __shared__ __align__(16) float smem[];
    uint2* wsp = (uint2*)smem;        // 1024 pairs (b0,b1) per (kk,t,g)
    float* st  = smem + 2048;         // 128 * EPITCH staging

    const int tid = threadIdx.x;
    const size_t eBase = (size_t)blockIdx.x * 128;

    // ---- stage weights paired: float pos i = kk*64 + (t*8+g)*2 + j,
    //      src col c = kk*8 + t + 4*j, src idx = c*8 + g. INV_SQRT3 on W1.
#pragma unroll
    for (int c = 0; c < 16; c++) {
        int i  = tid + c * 128;
        int kk = i >> 6;
        int p  = (i >> 1) & 31;
        int j  = i & 1;
        int t_ = p >> 3, g_ = p & 7;
        int src = (kk * 8 + t_ + 4 * j) * 8 + g_;
        float s = ((src >> 9) == 1) ? INV_SQRT3_F : 1.0f;
        ((u32*)smem)[i] = cvt_tf32(__ldg(wt + src) * s);
    }

    // ---- stage inputs (STS.128): x1*ALPHA at [0..31], x2 at [32..63] ----
    {
        const float4* g1 = (const float4*)(x1 + eBase * 32);
        const float4* g2 = (const float4*)(x2 + eBase * 32);
#pragma unroll
        for (int c = 0; c < 8; c++) {
            int lin = tid + c * 128;
            int e = lin >> 3, j = (lin & 7) << 2;
            float4 a = g1[lin];
            a.x *= ALPHA_F; a.y *= ALPHA_F; a.z *= ALPHA_F; a.w *= ALPHA_F;
            *(float4*)(st + e * EPITCH + j) = a;
            float4 b = g2[lin];
            *(float4*)(st + e * EPITCH + 32 + j) = b;
        }
    }
    __syncthreads();

    const int lane = tid & 31;
    const int g = lane >> 2;
    const int t = lane & 3;
    const int wBase = (tid >> 5) * 32;
    const int wIdx = t * 8 + g;

    float C0[2][4] = {};
    float C1[2][3][4] = {};

    // ---- caches for both rb halves: s1 (32F) and s2/v2 (32F) ----
    float s1l[2][8], s1h[2][8];
    float s2l[2][2], s2h[2][2], v2l[2][2][3], v2h[2][2][3];
#pragma unroll
    for (int rb = 0; rb < 2; rb++) {
        const float* Rlo = st + (wBase + rb * 16 + g) * EPITCH;
        const float* Rhi = Rlo + 8 * EPITCH;
        float4 lq0 = *(const float4*)(Rlo + 0);
        float4 lq1 = *(const float4*)(Rlo + 4);
        float4 hq0 = *(const float4*)(Rhi + 0);
        float4 hq1 = *(const float4*)(Rhi + 4);
        s1l[rb][0] = lq0.x; s1l[rb][1] = lq0.y; s1l[rb][2] = lq0.z; s1l[rb][3] = lq0.w;
        s1l[rb][4] = lq1.x; s1l[rb][5] = lq1.y; s1l[rb][6] = lq1.z; s1l[rb][7] = lq1.w;
        s1h[rb][0] = hq0.x; s1h[rb][1] = hq0.y; s1h[rb][2] = hq0.z; s1h[rb][3] = hq0.w;
        s1h[rb][4] = hq1.x; s1h[rb][5] = hq1.y; s1h[rb][6] = hq1.z; s1h[rb][7] = hq1.w;
#pragma unroll
        for (int j = 0; j < 2; j++) {
            int v = t + 4 * j;
            s2l[rb][j] = Rlo[32 + v];
            s2h[rb][j] = Rhi[32 + v];
#pragma unroll
            for (int k = 0; k < 3; k++) {
                v2l[rb][j][k] = Rlo[40 + v * 3 + k];
                v2h[rb][j][k] = Rhi[40 + v * 3 + k];
            }
        }
    }

    // ======== phase A: kk 0..7 — ONE weight load feeds BOTH rb halves ====
#pragma unroll
    for (int kk = 0; kk < 8; kk++) {
        uint2 wv1 = wsp[kk * 32 + wIdx];
        uint2 wv2 = wsp[(16 + kk) * 32 + wIdx];
#pragma unroll
        for (int rb = 0; rb < 2; rb++) {
            mma_tf32(C0[rb],
                     tf32_raw(s1l[rb][kk] * s2l[rb][0]),
                     tf32_raw(s1h[rb][kk] * s2h[rb][0]),
                     tf32_raw(s1l[rb][kk] * s2l[rb][1]),
                     tf32_raw(s1h[rb][kk] * s2h[rb][1]),
                     wv1);
#pragma unroll
            for (int k = 0; k < 3; k++)
                mma_tf32(C1[rb][k],
                         tf32_raw(s1l[rb][kk] * v2l[rb][0][k]),
                         tf32_raw(s1h[rb][kk] * v2h[rb][0][k]),
                         tf32_raw(s1l[rb][kk] * v2l[rb][1][k]),
                         tf32_raw(s1h[rb][kk] * v2h[rb][1][k]),
                         wv2);
        }
    }
    // s1 caches dead here

    // ======== phase B: kk 8..15 per rb (v1 cache for one rb at a time) ====
#pragma unroll
    for (int rb = 0; rb < 2; rb++) {
        const float* Rlo = st + (wBase + rb * 16 + g) * EPITCH;
        const float* Rhi = Rlo + 8 * EPITCH;
        float v1l[24], v1h[24];
#pragma unroll
        for (int q = 0; q < 6; q++) {
            float4 a = *(const float4*)(Rlo + 8 + 4 * q);
            v1l[4*q+0] = a.x; v1l[4*q+1] = a.y; v1l[4*q+2] = a.z; v1l[4*q+3] = a.w;
            float4 b = *(const float4*)(Rhi + 8 + 4 * q);
            v1h[4*q+0] = b.x; v1h[4*q+1] = b.y; v1h[4*q+2] = b.z; v1h[4*q+3] = b.w;
        }
#pragma unroll
        for (int kk = 8; kk < 16; kk++) {
            int u = kk - 8;
            uint2 wv1 = wsp[kk * 32 + wIdx];
            uint2 wv2 = wsp[(16 + kk) * 32 + wIdx];
            u32 a0 = tf32_raw(v1l[u*3+0] * v2l[rb][0][0] + v1l[u*3+1] * v2l[rb][0][1]
                              + v1l[u*3+2] * v2l[rb][0][2]);
            u32 a1 = tf32_raw(v1h[u*3+0] * v2h[rb][0][0] + v1h[u*3+1] * v2h[rb][0][1]
                              + v1h[u*3+2] * v2h[rb][0][2]);
            u32 a2 = tf32_raw(v1l[u*3+0] * v2l[rb][1][0] + v1l[u*3+1] * v2l[rb][1][1]
                              + v1l[u*3+2] * v2l[rb][1][2]);
            u32 a3 = tf32_raw(v1h[u*3+0] * v2h[rb][1][0] + v1h[u*3+1] * v2h[rb][1][1]
                              + v1h[u*3+2] * v2h[rb][1][2]);
            mma_tf32(C0[rb], a0, a1, a2, a3, wv1);
#pragma unroll
            for (int k = 0; k < 3; k++)
                mma_tf32(C1[rb][k],
                         tf32_raw(v1l[u*3+k] * s2l[rb][0]),
                         tf32_raw(v1h[u*3+k] * s2h[rb][0]),
                         tf32_raw(v1l[u*3+k] * s2l[rb][1]),
                         tf32_raw(v1h[u*3+k] * s2h[rb][1]),
                         wv2);
        }
    }

    // ======== vector stores into own staging rows (mapping as R13-R15) ====
#pragma unroll
    for (int rb = 0; rb < 2; rb++) {
        float* Rlo = st + (wBase + rb * 16 + g) * EPITCH;
        float* Rhi = Rlo + 8 * EPITCH;
        // C layout: c0:(g,2t) c1:(g,2t+1) c2:(g+8,2t) c3:(g+8,2t+1)
        *(float2*)(Rlo + 2 * t) = make_float2(C0[rb][0], C0[rb][1]);
        *(float2*)(Rhi + 2 * t) = make_float2(C0[rb][2], C0[rb][3]);
        *(float2*)(Rlo + 8 + 6 * t)     = make_float2(C1[rb][0][0], C1[rb][1][0]);
        *(float2*)(Rlo + 8 + 6 * t + 2) = make_float2(C1[rb][2][0], C1[rb][0][1]);
        *(float2*)(Rlo + 8 + 6 * t + 4) = make_float2(C1[rb][1][1], C1[rb][2][1]);
        *(float2*)(Rhi + 8 + 6 * t)     = make_float2(C1[rb][0][2], C1[rb][1][2]);
        *(float2*)(Rhi + 8 + 6 * t + 2) = make_float2(C1[rb][2][2], C1[rb][0][3]);
        *(float2*)(Rhi + 8 + 6 * t + 4) = make_float2(C1[rb][1][3], C1[rb][2][3]);
    }

    __syncthreads();

    // ---- coalesced drain (LDS.128 -> STG.128) ----
    {
        float4* go = (float4*)(out + eBase * 32);
#pragma unroll
        for (int c = 0; c < 8; c++) {
            int lin = tid + c * 128;
            int e = lin >> 3, j = (lin & 7) << 2;
            go[lin] = *(const float4*)(st + e * EPITCH + j);
        }
    }
}

extern "C" void kernel_launch(void* const* d_in, const int* in_sizes, int n_in,
                              void* d_out, int out_size)
{
    const float* x1 = (const float*)d_in[0];
    const float* x2 = (const float*)d_in[1];
    const float* wt = (const float*)d_in[2];
    float* out = (float*)d_out;

    int nelem  = out_size / 32;                            // 2^20
    int blocks = nelem / 128;                              // 128 elements/block
    size_t smem = (2048 + 128 * EPITCH) * sizeof(float);   // 43008 B

    static bool attr_set = false;
    if (!attr_set) {
        cudaFuncSetAttribute(fctp_kernel,
                             cudaFuncAttributeMaxDynamicSharedMemorySize,
                             (int)smem);
        attr_set = true;
    }
    fctp_kernel<<<blocks, 128, smem>>>(x1, x2, wt, out);
}